// round 14
// baseline (speedup 1.0000x reference)
#include <cuda_runtime.h>
#include <cuda_bf16.h>
#include <cstdint>

// 3x3 cross-correlation, 4096x4096 fp32, pad=1, stride=1.
// out[i][j] = sum_{dr,dc} w[dr*3+dc] * x[i+dr-1][j+dc-1] + bias
//
// R13 (v8 global accesses, best ncu 22.1us) with occupancy raised to
// 8 CTAs/SM via __launch_bounds__(128,8) (64-reg cap -> 32 warps/SM):
//  - CTA = 128 threads = 4 warps, warp strip = 256 wide x 16 rows.
//    Grid 16x64 = 1024 CTAs.
//  - lane owns 8 cols (32B-aligned): one ld.global.nc.v8.f32 per input row,
//    one st.global.cs.v8.f32 per output row.
//  - distance-2 register prefetch; exactly RPT+2 input rows per strip.

#define N_IMG 4096
#define TW    256
#define RPT   16
#define WARPS 4
#define TILE_H (RPT * WARPS)   // 64 rows per CTA
#define FULLMASK 0xFFFFFFFFu

struct Raw { float v0,v1,v2,v3,v4,v5,v6,v7; float e; };

__device__ __forceinline__ void ldg256(Raw& r, const float* p)
{
    asm volatile("ld.global.nc.v8.f32 {%0,%1,%2,%3,%4,%5,%6,%7}, [%8];"
                 : "=f"(r.v0), "=f"(r.v1), "=f"(r.v2), "=f"(r.v3),
                   "=f"(r.v4), "=f"(r.v5), "=f"(r.v6), "=f"(r.v7)
                 : "l"(p));
}

__device__ __forceinline__ void stg256_cs(float* p, const float* o)
{
    asm volatile("st.global.cs.v8.f32 [%0], {%1,%2,%3,%4,%5,%6,%7,%8};"
                 :: "l"(p),
                    "f"(o[0]), "f"(o[1]), "f"(o[2]), "f"(o[3]),
                    "f"(o[4]), "f"(o[5]), "f"(o[6]), "f"(o[7])
                 : "memory");
}

__device__ __forceinline__ Raw fetch_fast(const float* __restrict__ x,
                                          int grow, int c0, int lane)
{
    const float* rowp = x + (size_t)grow * N_IMG;
    Raw r;
    ldg256(r, rowp + c0);
    r.e = 0.f;
    if (lane == 0)  r.e = rowp[c0 - 1];
    if (lane == 31) r.e = rowp[c0 + 8];
    return r;
}

__device__ __forceinline__ Raw fetch_guard(const float* __restrict__ x,
                                           int grow, int c0, int lane)
{
    Raw r;
    r.v0=r.v1=r.v2=r.v3=r.v4=r.v5=r.v6=r.v7=0.f;
    r.e = 0.f;
    if ((unsigned)grow < (unsigned)N_IMG) {   // warp-uniform
        const float* rowp = x + (size_t)grow * N_IMG;
        ldg256(r, rowp + c0);
        if (lane == 0 && c0 > 0)          r.e = rowp[c0 - 1];
        if (lane == 31 && c0 + 8 < N_IMG) r.e = rowp[c0 + 8];
    }
    return r;
}

// raw -> 10-float shifted row (cols c0-1 .. c0+8)
__device__ __forceinline__ void expand(const Raw& q, int lane, float* v)
{
    float lf = __shfl_up_sync(FULLMASK, q.v7, 1);
    float rt = __shfl_down_sync(FULLMASK, q.v0, 1);
    if (lane == 0)  lf = q.e;
    if (lane == 31) rt = q.e;
    v[0]=lf;   v[1]=q.v0; v[2]=q.v1; v[3]=q.v2; v[4]=q.v3;
    v[5]=q.v4; v[6]=q.v5; v[7]=q.v6; v[8]=q.v7; v[9]=rt;
}

template<bool GUARD>
__device__ __forceinline__ void do_strip(const float* __restrict__ x,
                                         float* __restrict__ out,
                                         int row0, int tile_x, int lane,
                                         const float* w, float b)
{
    const int c0 = tile_x + lane * 8;
    float r[3][10];
    Raw pfA, pfB;

    if (GUARD) {
        Raw a = fetch_guard(x, row0 - 1, c0, lane);
        Raw q = fetch_guard(x, row0,     c0, lane);
        pfA   = fetch_guard(x, row0 + 1, c0, lane);
        pfB   = fetch_guard(x, row0 + 2, c0, lane);
        expand(a, lane, r[0]);
        expand(q, lane, r[1]);
    } else {
        Raw a = fetch_fast(x, row0 - 1, c0, lane);
        Raw q = fetch_fast(x, row0,     c0, lane);
        pfA   = fetch_fast(x, row0 + 1, c0, lane);
        pfB   = fetch_fast(x, row0 + 2, c0, lane);
        expand(a, lane, r[0]);
        expand(q, lane, r[1]);
    }

    #pragma unroll
    for (int i = 0; i < RPT; i++) {
        // row (row0+i+1) becomes resident
        expand(pfA, lane, r[(i + 2) % 3]);
        pfA = pfB;

        // fetch row (row0+i+3), consumed at iter i+2; gate so exactly
        // RPT+2 input rows are read per strip
        if (i <= RPT - 3) {
            if (GUARD) pfB = fetch_guard(x, row0 + i + 3, c0, lane);
            else       pfB = fetch_fast (x, row0 + i + 3, c0, lane);
        }

        const float* r0 = r[ i      % 3];
        const float* r1 = r[(i + 1) % 3];
        const float* r2 = r[(i + 2) % 3];

        float o[8];
        #pragma unroll
        for (int j = 0; j < 8; j++) {
            float acc = b;
            acc = fmaf(w[0], r0[j    ], acc);
            acc = fmaf(w[1], r0[j + 1], acc);
            acc = fmaf(w[2], r0[j + 2], acc);
            acc = fmaf(w[3], r1[j    ], acc);
            acc = fmaf(w[4], r1[j + 1], acc);
            acc = fmaf(w[5], r1[j + 2], acc);
            acc = fmaf(w[6], r2[j    ], acc);
            acc = fmaf(w[7], r2[j + 1], acc);
            acc = fmaf(w[8], r2[j + 2], acc);
            o[j] = acc;
        }

        stg256_cs(out + (size_t)(row0 + i) * N_IMG + c0, o);
    }
}

__global__ __launch_bounds__(128, 8)
void conv3x3_v8occ_kernel(const float* __restrict__ x,
                          const float* __restrict__ w9,
                          const float* __restrict__ bias,
                          float* __restrict__ out)
{
    const int lane   = threadIdx.x & 31;
    const int warp   = threadIdx.x >> 5;
    const int tile_x = blockIdx.x * TW;
    const int row0   = blockIdx.y * TILE_H + warp * RPT;

    float w[9];
    #pragma unroll
    for (int i = 0; i < 9; i++) w[i] = __ldg(&w9[i]);
    const float b = __ldg(&bias[0]);

    const bool guard = (row0 == 0) | (row0 + RPT >= N_IMG) |
                       (tile_x == 0) | (tile_x + TW >= N_IMG);

    if (!guard)
        do_strip<false>(x, out, row0, tile_x, lane, w, b);
    else
        do_strip<true >(x, out, row0, tile_x, lane, w, b);
}

extern "C" void kernel_launch(void* const* d_in, const int* in_sizes, int n_in,
                              void* d_out, int out_size)
{
    const float* x    = (const float*)d_in[0];   // 4096*4096
    const float* w9   = (const float*)d_in[1];   // 9
    const float* bias = (const float*)d_in[2];   // 1
    float* out        = (float*)d_out;           // 4096*4096

    dim3 block(128, 1, 1);
    dim3 grid(N_IMG / TW, N_IMG / TILE_H, 1);    // 16 x 64 = 1024 CTAs
    conv3x3_v8occ_kernel<<<grid, block>>>(x, w9, bias, out);
}

// round 15
// speedup vs baseline: 1.2760x; 1.2760x over previous
#include <cuda_runtime.h>
#include <cuda_bf16.h>
#include <cstdint>

// 3x3 cross-correlation, 4096x4096 fp32, pad=1, stride=1.
// out[i][j] = sum_{dr,dc} w[dr*3+dc] * x[i+dr-1][j+dc-1] + bias
//
// R13 (best: ncu 22.1us) + merged edge load:
//  - CTA = 128 threads = 4 warps, warp strip = 256 wide x 16 rows.
//    Grid 16x64 = 1024 CTAs, 7 CTAs/SM (72 regs) -> 28 warps/SM.
//  - lane owns 8 cols (32B-aligned): one ld.global.nc.v8.f32 per input row,
//    one st.global.cs.v8.f32 per output row.
//  - edge halo: ONE predicated scalar LDG shared by lanes 0/31 (address
//    selected arithmetically) instead of two.
//  - distance-2 register prefetch; exactly RPT+2 input rows per strip.

#define N_IMG 4096
#define TW    256
#define RPT   16
#define WARPS 4
#define TILE_H (RPT * WARPS)   // 64 rows per CTA
#define FULLMASK 0xFFFFFFFFu

struct Raw { float v0,v1,v2,v3,v4,v5,v6,v7; float e; };

__device__ __forceinline__ void ldg256(Raw& r, const float* p)
{
    asm volatile("ld.global.nc.v8.f32 {%0,%1,%2,%3,%4,%5,%6,%7}, [%8];"
                 : "=f"(r.v0), "=f"(r.v1), "=f"(r.v2), "=f"(r.v3),
                   "=f"(r.v4), "=f"(r.v5), "=f"(r.v6), "=f"(r.v7)
                 : "l"(p));
}

__device__ __forceinline__ void stg256_cs(float* p, const float* o)
{
    asm volatile("st.global.cs.v8.f32 [%0], {%1,%2,%3,%4,%5,%6,%7,%8};"
                 :: "l"(p),
                    "f"(o[0]), "f"(o[1]), "f"(o[2]), "f"(o[3]),
                    "f"(o[4]), "f"(o[5]), "f"(o[6]), "f"(o[7])
                 : "memory");
}

__device__ __forceinline__ Raw fetch_fast(const float* __restrict__ x,
                                          int grow, int c0, int lane)
{
    const float* rowp = x + (size_t)grow * N_IMG;
    Raw r;
    ldg256(r, rowp + c0);
    r.e = 0.f;
    // one predicated LDG serves both edge lanes
    const int ec = (lane == 0) ? (c0 - 1) : (c0 + 8);
    if ((lane == 0) | (lane == 31)) r.e = rowp[ec];
    return r;
}

__device__ __forceinline__ Raw fetch_guard(const float* __restrict__ x,
                                           int grow, int c0, int lane)
{
    Raw r;
    r.v0=r.v1=r.v2=r.v3=r.v4=r.v5=r.v6=r.v7=0.f;
    r.e = 0.f;
    if ((unsigned)grow < (unsigned)N_IMG) {   // warp-uniform
        const float* rowp = x + (size_t)grow * N_IMG;
        ldg256(r, rowp + c0);
        const int ec = (lane == 0) ? (c0 - 1) : (c0 + 8);
        const bool edge_ok = ((lane == 0) & (c0 > 0)) |
                             ((lane == 31) & (c0 + 8 < N_IMG));
        if (edge_ok) r.e = rowp[ec];
    }
    return r;
}

// raw -> 10-float shifted row (cols c0-1 .. c0+8)
__device__ __forceinline__ void expand(const Raw& q, int lane, float* v)
{
    float lf = __shfl_up_sync(FULLMASK, q.v7, 1);
    float rt = __shfl_down_sync(FULLMASK, q.v0, 1);
    if (lane == 0)  lf = q.e;
    if (lane == 31) rt = q.e;
    v[0]=lf;   v[1]=q.v0; v[2]=q.v1; v[3]=q.v2; v[4]=q.v3;
    v[5]=q.v4; v[6]=q.v5; v[7]=q.v6; v[8]=q.v7; v[9]=rt;
}

template<bool GUARD>
__device__ __forceinline__ void do_strip(const float* __restrict__ x,
                                         float* __restrict__ out,
                                         int row0, int tile_x, int lane,
                                         const float* w, float b)
{
    const int c0 = tile_x + lane * 8;
    float r[3][10];
    Raw pfA, pfB;

    if (GUARD) {
        Raw a = fetch_guard(x, row0 - 1, c0, lane);
        Raw q = fetch_guard(x, row0,     c0, lane);
        pfA   = fetch_guard(x, row0 + 1, c0, lane);
        pfB   = fetch_guard(x, row0 + 2, c0, lane);
        expand(a, lane, r[0]);
        expand(q, lane, r[1]);
    } else {
        Raw a = fetch_fast(x, row0 - 1, c0, lane);
        Raw q = fetch_fast(x, row0,     c0, lane);
        pfA   = fetch_fast(x, row0 + 1, c0, lane);
        pfB   = fetch_fast(x, row0 + 2, c0, lane);
        expand(a, lane, r[0]);
        expand(q, lane, r[1]);
    }

    #pragma unroll
    for (int i = 0; i < RPT; i++) {
        // row (row0+i+1) becomes resident
        expand(pfA, lane, r[(i + 2) % 3]);
        pfA = pfB;

        // fetch row (row0+i+3), consumed at iter i+2; gate so exactly
        // RPT+2 input rows are read per strip
        if (i <= RPT - 3) {
            if (GUARD) pfB = fetch_guard(x, row0 + i + 3, c0, lane);
            else       pfB = fetch_fast (x, row0 + i + 3, c0, lane);
        }

        const float* r0 = r[ i      % 3];
        const float* r1 = r[(i + 1) % 3];
        const float* r2 = r[(i + 2) % 3];

        float o[8];
        #pragma unroll
        for (int j = 0; j < 8; j++) {
            float acc = b;
            acc = fmaf(w[0], r0[j    ], acc);
            acc = fmaf(w[1], r0[j + 1], acc);
            acc = fmaf(w[2], r0[j + 2], acc);
            acc = fmaf(w[3], r1[j    ], acc);
            acc = fmaf(w[4], r1[j + 1], acc);
            acc = fmaf(w[5], r1[j + 2], acc);
            acc = fmaf(w[6], r2[j    ], acc);
            acc = fmaf(w[7], r2[j + 1], acc);
            acc = fmaf(w[8], r2[j + 2], acc);
            o[j] = acc;
        }

        stg256_cs(out + (size_t)(row0 + i) * N_IMG + c0, o);
    }
}

__global__ __launch_bounds__(128, 7)
void conv3x3_v8b_kernel(const float* __restrict__ x,
                        const float* __restrict__ w9,
                        const float* __restrict__ bias,
                        float* __restrict__ out)
{
    const int lane   = threadIdx.x & 31;
    const int warp   = threadIdx.x >> 5;
    const int tile_x = blockIdx.x * TW;
    const int row0   = blockIdx.y * TILE_H + warp * RPT;

    float w[9];
    #pragma unroll
    for (int i = 0; i < 9; i++) w[i] = __ldg(&w9[i]);
    const float b = __ldg(&bias[0]);

    const bool guard = (row0 == 0) | (row0 + RPT >= N_IMG) |
                       (tile_x == 0) | (tile_x + TW >= N_IMG);

    if (!guard)
        do_strip<false>(x, out, row0, tile_x, lane, w, b);
    else
        do_strip<true >(x, out, row0, tile_x, lane, w, b);
}

extern "C" void kernel_launch(void* const* d_in, const int* in_sizes, int n_in,
                              void* d_out, int out_size)
{
    const float* x    = (const float*)d_in[0];   // 4096*4096
    const float* w9   = (const float*)d_in[1];   // 9
    const float* bias = (const float*)d_in[2];   // 1
    float* out        = (float*)d_out;           // 4096*4096

    dim3 block(128, 1, 1);
    dim3 grid(N_IMG / TW, N_IMG / TILE_H, 1);    // 16 x 64 = 1024 CTAs
    conv3x3_v8b_kernel<<<grid, block>>>(x, w9, bias, out);
}